// round 1
// baseline (speedup 1.0000x reference)
#include <cuda_runtime.h>

// LIF membrane update:
//   mem_t = (mem_{t-1} - spike_{t-1} * 0.5) * 0.25 + x_t
//   spike_t = rint(clamp(mem_t, 0, 1))   (round-half-to-even, matches jnp.round)
// x: [T=4, N], out: [T=4, N], per-element independent recurrence over t.

#define DECAY 0.25f
#define T_STEPS 4

__global__ __launch_bounds__(256) void lif_kernel(const float4* __restrict__ x,
                                                  float4* __restrict__ out,
                                                  int n4) {
    int i = blockIdx.x * blockDim.x + threadIdx.x;
    if (i >= n4) return;

    float4 mem = make_float4(0.f, 0.f, 0.f, 0.f);
    float4 spk = make_float4(0.f, 0.f, 0.f, 0.f);

#pragma unroll
    for (int t = 0; t < T_STEPS; t++) {
        float4 xi = x[(size_t)t * n4 + i];

        mem.x = fmaf(mem.x - spk.x * 0.5f, DECAY, xi.x);
        mem.y = fmaf(mem.y - spk.y * 0.5f, DECAY, xi.y);
        mem.z = fmaf(mem.z - spk.z * 0.5f, DECAY, xi.z);
        mem.w = fmaf(mem.w - spk.w * 0.5f, DECAY, xi.w);

        spk.x = rintf(fminf(fmaxf(mem.x, 0.f), 1.f));
        spk.y = rintf(fminf(fmaxf(mem.y, 0.f), 1.f));
        spk.z = rintf(fminf(fmaxf(mem.z, 0.f), 1.f));
        spk.w = rintf(fminf(fmaxf(mem.w, 0.f), 1.f));

        out[(size_t)t * n4 + i] = spk;
    }
}

extern "C" void kernel_launch(void* const* d_in, const int* in_sizes, int n_in,
                              void* d_out, int out_size) {
    const float4* x = (const float4*)d_in[0];
    float4* out = (float4*)d_out;

    int n_total = in_sizes[0];        // T * N
    int n4 = (n_total / T_STEPS) / 4; // float4 elements per timestep

    int threads = 256;
    int blocks = (n4 + threads - 1) / threads;
    lif_kernel<<<blocks, threads>>>(x, out, n4);
}